// round 12
// baseline (speedup 1.0000x reference)
#include <cuda_runtime.h>
#include <cuda_bf16.h>
#include <math.h>
#include <stdint.h>

// LSTM T=512, B=64, I=H=512 on GB300 (sm_103a via compute_103, HMMA path).
// Persistent 128-CTA x 256-thread kernel. CTA = cg*4+kg: cg owns 64 gate cols,
// kg owns K-slice of 128 (for BOTH the x half [k=kg*128] and h half [k=512+kg*128]).
// Software pipeline: x-partials for step t+1 are computed at iteration t, in the
// slack before the elem(t-1) wait -> x-GEMM off the critical path.
// R12 fix vs R11: stage_tile staged only HALF of each 128-bf16 row (8 of 16
// 16B-units); GEMM read 128B of garbage SMEM per row -> rel_err 0.75. Fixed.

#define T_STEPS 512
#define B_SZ    64
#define H_SZ    512
#define I_SZ    512
#define G4      2048
#define NCTA    128
#define NTHR    256
#define KSL     128              // K-slice per kg per half

#define STRB    272              // tile row stride bytes (128 bf16 + 16 pad)
#define TILEB   (64 * STRB)      // 17408
#define SM_BIAS 0
#define SM_AX_HI 64
#define SM_AX_LO (SM_AX_HI + TILEB)
#define SM_AH_HI (SM_AX_LO + TILEB)
#define SM_AH_LO (SM_AH_HI + TILEB)
#define SM_WX_HI (SM_AH_LO + TILEB)
#define SM_WX_LO (SM_WX_HI + TILEB)
#define SM_WH_HI (SM_WX_LO + TILEB)
#define SM_WH_LO (SM_WH_HI + TILEB)
#define SM_TOTAL (SM_WH_LO + TILEB)   // 139328

__device__ __align__(16) __nv_bfloat16 g_x_hi[T_STEPS * B_SZ * I_SZ];
__device__ __align__(16) __nv_bfloat16 g_x_lo[T_STEPS * B_SZ * I_SZ];
__device__ __align__(16) __nv_bfloat16 g_h_hi[B_SZ * H_SZ];
__device__ __align__(16) __nv_bfloat16 g_h_lo[B_SZ * H_SZ];
__device__ float g_xp[3][4][G4 * B_SZ];   // x partials, [slot][kg][col*64+b]
__device__ float g_hp[4][G4 * B_SZ];      // h partials, [kg][col*64+b]
__device__ unsigned g_init;
__device__ unsigned g_ph;
__device__ unsigned g_elem;

__device__ __forceinline__ float sigmoidf_fast(float x) {
    return 1.0f / (1.0f + __expf(-x));
}
__device__ __forceinline__ float tanhf_fast(float x) {
    return 2.0f / (1.0f + __expf(-2.0f * x)) - 1.0f;
}
__device__ __forceinline__ void mma_bf16(float* d, const uint32_t* a, const uint32_t* b) {
    asm volatile(
        "mma.sync.aligned.m16n8k16.row.col.f32.bf16.bf16.f32 "
        "{%0,%1,%2,%3}, {%4,%5,%6,%7}, {%8,%9}, {%0,%1,%2,%3};"
        : "+f"(d[0]), "+f"(d[1]), "+f"(d[2]), "+f"(d[3])
        : "r"(a[0]), "r"(a[1]), "r"(a[2]), "r"(a[3]), "r"(b[0]), "r"(b[1]));
}
__device__ __forceinline__ void signal(unsigned* ctr) {
    asm volatile("red.release.gpu.add.u32 [%0], 1;" :: "l"(ctr) : "memory");
}
__device__ __forceinline__ void wait_ge(unsigned* ctr, unsigned target) {
    unsigned v;
    asm volatile("ld.acquire.gpu.u32 %0, [%1];" : "=r"(v) : "l"(ctr) : "memory");
    while (v < target) {
        __nanosleep(64);
        asm volatile("ld.acquire.gpu.u32 %0, [%1];" : "=r"(v) : "l"(ctr) : "memory");
    }
}

// 64x64x128 3-pass bf16-split GEMM from SMEM tiles. Warp tile M16xN32.
__device__ __forceinline__ void gemm_tile(const char* smem, int aoff_hi, int aoff_lo,
                                          int woff_hi, int woff_lo,
                                          int m_base, int n_base, int grp, int tg,
                                          float acc[4][4]) {
    const char* arow = smem + (m_base + grp) * STRB + tg * 4;
    #pragma unroll
    for (int ks = 0; ks < 8; ks++) {
        const int kb = ks * 32;
        uint32_t a_hi[4], a_lo[4];
        a_hi[0] = *(const uint32_t*)(arow + aoff_hi + kb);
        a_hi[1] = *(const uint32_t*)(arow + aoff_hi + 8 * STRB + kb);
        a_hi[2] = *(const uint32_t*)(arow + aoff_hi + kb + 16);
        a_hi[3] = *(const uint32_t*)(arow + aoff_hi + 8 * STRB + kb + 16);
        a_lo[0] = *(const uint32_t*)(arow + aoff_lo + kb);
        a_lo[1] = *(const uint32_t*)(arow + aoff_lo + 8 * STRB + kb);
        a_lo[2] = *(const uint32_t*)(arow + aoff_lo + kb + 16);
        a_lo[3] = *(const uint32_t*)(arow + aoff_lo + 8 * STRB + kb + 16);
        #pragma unroll
        for (int nt = 0; nt < 4; nt++) {
            const char* brow = smem + (n_base + nt * 8 + grp) * STRB + tg * 4 + kb;
            uint32_t b_hi[2], b_lo[2];
            b_hi[0] = *(const uint32_t*)(brow + woff_hi);
            b_hi[1] = *(const uint32_t*)(brow + woff_hi + 16);
            b_lo[0] = *(const uint32_t*)(brow + woff_lo);
            b_lo[1] = *(const uint32_t*)(brow + woff_lo + 16);
            mma_bf16(acc[nt], a_hi, b_hi);
            mma_bf16(acc[nt], a_hi, b_lo);
            mma_bf16(acc[nt], a_lo, b_hi);
        }
    }
}

// stage a 64x128 bf16 hi/lo slice (row stride 512 in gmem) into SMEM tiles.
// 64 rows x 16 16B-units = 1024 units per array (R12: was 8 units/row — bug).
__device__ __forceinline__ void stage_tile(char* smem, int dst_hi, int dst_lo,
                                           const __nv_bfloat16* sh,
                                           const __nv_bfloat16* sl, int tid) {
    #pragma unroll
    for (int it = 0; it < 4; it++) {
        int idx = tid + it * NTHR;       // 0..1023
        int r   = idx >> 4;              // 0..63
        int c16 = idx & 15;              // 16B unit (16 per row = 128 bf16)
        uint4 vh = *(const uint4*)(sh + (size_t)r * 512 + c16 * 8);
        uint4 vl = *(const uint4*)(sl + (size_t)r * 512 + c16 * 8);
        int o = r * STRB + c16 * 16;
        *(uint4*)(smem + dst_hi + o) = vh;
        *(uint4*)(smem + dst_lo + o) = vl;
    }
}

extern "C" __global__ void __launch_bounds__(NTHR, 1)
lstm_pipe_kernel(const float* __restrict__ x,
                 const float* __restrict__ hidden0,
                 const float* __restrict__ cell0,
                 const float* __restrict__ W,
                 const float* __restrict__ bias,
                 float* __restrict__ out)
{
    extern __shared__ char smem[];
    float* sbias = (float*)(smem + SM_BIAS);

    const int tid = threadIdx.x;
    const int bid = blockIdx.x;
    const int cg  = bid >> 2;
    const int kg  = bid & 3;
    const int wid = tid >> 5;
    const int lid = tid & 31;
    const int grp = lid >> 2;
    const int tg  = lid & 3;
    const int m_base = (wid >> 1) * 16;   // 4 M-warps
    const int n_base = (wid & 1) * 32;    // 2 N-warps

    // elementwise ownership (R3 mapping; 4-sector gathers)
    const int eb  = tid >> 2;
    const int ejj = tid & 3;
    const int ej  = bid * 4 + ejj;

    // ---- init: W_x and W_h slices -> SMEM hi/lo [n][k] (one-time) ----
    {
        const float* wx = W + (size_t)(kg * KSL) * G4 + cg * 64;
        const float* wh = W + (size_t)(512 + kg * KSL) * G4 + cg * 64;
        for (int idx = tid; idx < KSL * 64; idx += NTHR) {
            int n = idx & 63;
            int k = idx >> 6;
            int o = n * STRB + k * 2;
            float w0 = wx[(size_t)k * G4 + n];
            __nv_bfloat16 h0 = __float2bfloat16_rn(w0);
            *(__nv_bfloat16*)(smem + SM_WX_HI + o) = h0;
            *(__nv_bfloat16*)(smem + SM_WX_LO + o) = __float2bfloat16_rn(w0 - __bfloat162float(h0));
            float w1 = wh[(size_t)k * G4 + n];
            __nv_bfloat16 h1 = __float2bfloat16_rn(w1);
            *(__nv_bfloat16*)(smem + SM_WH_HI + o) = h1;
            *(__nv_bfloat16*)(smem + SM_WH_LO + o) = __float2bfloat16_rn(w1 - __bfloat162float(h1));
        }
    }
    if (tid < 16) {
        int gate = tid >> 2;
        int jj   = tid & 3;
        sbias[tid] = bias[gate * H_SZ + bid * 4 + jj];
    }
    // ---- pre-split x -> bf16 hi/lo (grid-strided) ----
    {
        const float4* x4 = (const float4*)x;
        const int n4 = T_STEPS * B_SZ * I_SZ / 4;
        for (int i = bid * NTHR + tid; i < n4; i += NCTA * NTHR) {
            float4 v = x4[i];
            __nv_bfloat16 h0 = __float2bfloat16_rn(v.x);
            __nv_bfloat16 h1 = __float2bfloat16_rn(v.y);
            __nv_bfloat16 h2 = __float2bfloat16_rn(v.z);
            __nv_bfloat16 h3 = __float2bfloat16_rn(v.w);
            __nv_bfloat162* dh = (__nv_bfloat162*)(g_x_hi + 4 * (size_t)i);
            dh[0] = __nv_bfloat162(h0, h1);
            dh[1] = __nv_bfloat162(h2, h3);
            __nv_bfloat162* dl = (__nv_bfloat162*)(g_x_lo + 4 * (size_t)i);
            dl[0] = __nv_bfloat162(__float2bfloat16_rn(v.x - __bfloat162float(h0)),
                                   __float2bfloat16_rn(v.y - __bfloat162float(h1)));
            dl[1] = __nv_bfloat162(__float2bfloat16_rn(v.z - __bfloat162float(h2)),
                                   __float2bfloat16_rn(v.w - __bfloat162float(h3)));
        }
    }
    // ---- state init ----
    float c_state = cell0[eb * H_SZ + ej];
    {
        float hv = hidden0[eb * H_SZ + ej];
        __nv_bfloat16 hh = __float2bfloat16_rn(hv);
        g_h_hi[eb * H_SZ + ej] = hh;
        g_h_lo[eb * H_SZ + ej] = __float2bfloat16_rn(hv - __bfloat162float(hh));
    }
    float h_last = 0.0f;

    // ---- init grid barrier: presplit + h0 visible everywhere ----
    __syncthreads();
    if (tid == 0) {
        signal(&g_init);
        wait_ge(&g_init, NCTA);
    }
    __syncthreads();

    // ---- prologue: xpart(0) into slot 0 ----
    {
        size_t off = (size_t)kg * KSL;   // t=0
        stage_tile(smem, SM_AX_HI, SM_AX_LO, g_x_hi + off, g_x_lo + off, tid);
        __syncthreads();
        float acc[4][4];
        #pragma unroll
        for (int i = 0; i < 4; i++) { acc[i][0]=0.f; acc[i][1]=0.f; acc[i][2]=0.f; acc[i][3]=0.f; }
        gemm_tile(smem, SM_AX_HI, SM_AX_LO, SM_WX_HI, SM_WX_LO, m_base, n_base, grp, tg, acc);
        float* xp = g_xp[0][kg];
        #pragma unroll
        for (int nt = 0; nt < 4; nt++) {
            int col = cg * 64 + n_base + nt * 8 + tg * 2;
            int b0  = m_base + grp;
            xp[col * B_SZ + b0]           = acc[nt][0];
            xp[(col + 1) * B_SZ + b0]     = acc[nt][1];
            xp[col * B_SZ + b0 + 8]       = acc[nt][2];
            xp[(col + 1) * B_SZ + b0 + 8] = acc[nt][3];
        }
    }
    __syncthreads();
    if (tid == 0) signal(&g_elem);   // xpart(0) + h0 published

    // ---- time loop ----
    for (int t = 0; t < T_STEPS; t++) {
        // 1) x-block: produce xpart(t+1) into slot (t+1)%3 (fills the wait slack)
        if (t + 1 < T_STEPS) {
            size_t off = (size_t)(t + 1) * B_SZ * I_SZ + kg * KSL;
            stage_tile(smem, SM_AX_HI, SM_AX_LO, g_x_hi + off, g_x_lo + off, tid);
            __syncthreads();
            float acc[4][4];
            #pragma unroll
            for (int i = 0; i < 4; i++) { acc[i][0]=0.f; acc[i][1]=0.f; acc[i][2]=0.f; acc[i][3]=0.f; }
            gemm_tile(smem, SM_AX_HI, SM_AX_LO, SM_WX_HI, SM_WX_LO, m_base, n_base, grp, tg, acc);
            float* xp = g_xp[(t + 1) % 3][kg];
            #pragma unroll
            for (int nt = 0; nt < 4; nt++) {
                int col = cg * 64 + n_base + nt * 8 + tg * 2;
                int b0  = m_base + grp;
                xp[col * B_SZ + b0]           = acc[nt][0];
                xp[(col + 1) * B_SZ + b0]     = acc[nt][1];
                xp[col * B_SZ + b0 + 8]       = acc[nt][2];
                xp[(col + 1) * B_SZ + b0 + 8] = acc[nt][3];
            }
            __syncthreads();
        }

        // 2) wait elem(t-1) done everywhere (h(t-1) + xpart(t) visible via acquire)
        if (tid == 0) wait_ge(&g_elem, (unsigned)(NCTA * (t + 1)));
        __syncthreads();

        // 3) h-block: stage h slice, GEMM, hpart(t), signal + wait g_ph
        {
            stage_tile(smem, SM_AH_HI, SM_AH_LO, g_h_hi + kg * KSL, g_h_lo + kg * KSL, tid);
            __syncthreads();
            float acc[4][4];
            #pragma unroll
            for (int i = 0; i < 4; i++) { acc[i][0]=0.f; acc[i][1]=0.f; acc[i][2]=0.f; acc[i][3]=0.f; }
            gemm_tile(smem, SM_AH_HI, SM_AH_LO, SM_WH_HI, SM_WH_LO, m_base, n_base, grp, tg, acc);
            float* hp = g_hp[kg];
            #pragma unroll
            for (int nt = 0; nt < 4; nt++) {
                int col = cg * 64 + n_base + nt * 8 + tg * 2;
                int b0  = m_base + grp;
                hp[col * B_SZ + b0]           = acc[nt][0];
                hp[(col + 1) * B_SZ + b0]     = acc[nt][1];
                hp[col * B_SZ + b0 + 8]       = acc[nt][2];
                hp[(col + 1) * B_SZ + b0 + 8] = acc[nt][3];
            }
        }
        __syncthreads();
        if (tid == 0) {
            signal(&g_ph);
            wait_ge(&g_ph, (unsigned)(NCTA * (t + 1)));
        }
        __syncthreads();

        // 4) elementwise: gates = sum_kg (xpart + hpart) + bias
        {
            const float* xp0 = g_xp[t % 3][0];
            const float* xp1 = g_xp[t % 3][1];
            const float* xp2 = g_xp[t % 3][2];
            const float* xp3 = g_xp[t % 3][3];
            float gate[4];
            #pragma unroll
            for (int g = 0; g < 4; g++) {
                int idx = (g * H_SZ + ej) * B_SZ + eb;
                gate[g] = sbias[g * 4 + ejj]
                        + xp0[idx] + xp1[idx] + xp2[idx] + xp3[idx]
                        + g_hp[0][idx] + g_hp[1][idx] + g_hp[2][idx] + g_hp[3][idx];
            }
            float f  = sigmoidf_fast(gate[0]);
            float ii = sigmoidf_fast(gate[1]);
            float cd = tanhf_fast(gate[2]);
            float o  = sigmoidf_fast(gate[3]);
            c_state = f * c_state + ii * cd;
            float h = o * tanhf_fast(c_state);
            h_last = h;
            __nv_bfloat16 hh = __float2bfloat16_rn(h);
            g_h_hi[eb * H_SZ + ej] = hh;
            g_h_lo[eb * H_SZ + ej] = __float2bfloat16_rn(h - __bfloat162float(hh));
            out[(size_t)t * (B_SZ * H_SZ) + eb * H_SZ + ej] = h;
        }
        __syncthreads();
        if (tid == 0) signal(&g_elem);   // no wait here; next iter's step 2 polls
    }

    // final states
    {
        size_t base = (size_t)T_STEPS * B_SZ * H_SZ;
        out[base + eb * H_SZ + ej] = h_last;
        out[base + B_SZ * H_SZ + eb * H_SZ + ej] = c_state;
    }
}

extern "C" void kernel_launch(void* const* d_in, const int* in_sizes, int n_in,
                              void* d_out, int out_size)
{
    (void)in_sizes; (void)n_in; (void)out_size;
    const float* x       = (const float*)d_in[0];
    const float* hidden0 = (const float*)d_in[1];
    const float* cell0   = (const float*)d_in[2];
    const float* W       = (const float*)d_in[3];
    const float* bias    = (const float*)d_in[4];
    float* out = (float*)d_out;

    void* a0 = nullptr; void* a1 = nullptr; void* a2 = nullptr;
    cudaGetSymbolAddress(&a0, g_ph);
    cudaGetSymbolAddress(&a1, g_elem);
    cudaGetSymbolAddress(&a2, g_init);
    cudaMemsetAsync(a0, 0, sizeof(unsigned));
    cudaMemsetAsync(a1, 0, sizeof(unsigned));
    cudaMemsetAsync(a2, 0, sizeof(unsigned));

    cudaFuncSetAttribute(lstm_pipe_kernel,
                         cudaFuncAttributeMaxDynamicSharedMemorySize, SM_TOTAL);

    lstm_pipe_kernel<<<NCTA, NTHR, SM_TOTAL>>>(x, hidden0, cell0, W, bias, out);
}

// round 13
// speedup vs baseline: 1.0567x; 1.0567x over previous
#include <cuda_runtime.h>
#include <cuda_bf16.h>
#include <math.h>
#include <stdint.h>

// LSTM T=512, B=64, I=H=512 on GB300 (sm_103a via compute_103, HMMA path).
// R13: localized synchronization. Gate-col ownership remapped so CTA cg owns
// cols {g*512 + cg*16 + u : g<4, u<16}; then:
//  - partial exchange (ph): per-cg counter, 4 arrivals (the kg partners)
//  - h availability (elem): per-cg counters; stager of h-slice [kg*128,+128)
//    waits on 8 cgs [kg*8, kg*8+8) only.
// hp and h are parity double-buffered (reuse distance 2; ordering proven via
// the ph/elem happens-before chains). xp triple-buffered as in R12.
// GEMM/staging identical to R12 (64x64x128 3-pass bf16-split, padded smem).

#define T_STEPS 512
#define B_SZ    64
#define H_SZ    512
#define I_SZ    512
#define G4      2048
#define NCTA    128
#define NTHR    256
#define KSL     128

#define STRB    272
#define TILEB   (64 * STRB)
#define SM_BIAS 0
#define SM_AX_HI 64
#define SM_AX_LO (SM_AX_HI + TILEB)
#define SM_AH_HI (SM_AX_LO + TILEB)
#define SM_AH_LO (SM_AH_HI + TILEB)
#define SM_WX_HI (SM_AH_LO + TILEB)
#define SM_WX_LO (SM_WX_HI + TILEB)
#define SM_WH_HI (SM_WX_LO + TILEB)
#define SM_WH_LO (SM_WH_HI + TILEB)
#define SM_TOTAL (SM_WH_LO + TILEB)   // 139328

#define CPAD 32    // counter padding (128B lines)

__device__ __align__(16) __nv_bfloat16 g_x_hi[T_STEPS * B_SZ * I_SZ];
__device__ __align__(16) __nv_bfloat16 g_x_lo[T_STEPS * B_SZ * I_SZ];
__device__ __align__(16) __nv_bfloat16 g_h_hi[2][B_SZ * H_SZ];   // parity buffers
__device__ __align__(16) __nv_bfloat16 g_h_lo[2][B_SZ * H_SZ];
__device__ float g_xp[3][4][G4 * B_SZ];      // [slot][kg][col'*64+b], col' = cg*64+n'
__device__ float g_hp[2][4][G4 * B_SZ];      // [parity][kg][col'*64+b]
__device__ unsigned g_init;
__device__ unsigned g_ph[32 * CPAD];         // per-cg, 4 arrivals/step
__device__ unsigned g_elem[32 * CPAD];       // per-cg, 4 arrivals/step

__device__ __forceinline__ float sigmoidf_fast(float x) {
    return 1.0f / (1.0f + __expf(-x));
}
__device__ __forceinline__ float tanhf_fast(float x) {
    return 2.0f / (1.0f + __expf(-2.0f * x)) - 1.0f;
}
__device__ __forceinline__ void mma_bf16(float* d, const uint32_t* a, const uint32_t* b) {
    asm volatile(
        "mma.sync.aligned.m16n8k16.row.col.f32.bf16.bf16.f32 "
        "{%0,%1,%2,%3}, {%4,%5,%6,%7}, {%8,%9}, {%0,%1,%2,%3};"
        : "+f"(d[0]), "+f"(d[1]), "+f"(d[2]), "+f"(d[3])
        : "r"(a[0]), "r"(a[1]), "r"(a[2]), "r"(a[3]), "r"(b[0]), "r"(b[1]));
}
__device__ __forceinline__ void signal(unsigned* ctr) {
    asm volatile("red.release.gpu.add.u32 [%0], 1;" :: "l"(ctr) : "memory");
}
__device__ __forceinline__ void wait_ge(unsigned* ctr, unsigned target) {
    unsigned v;
    asm volatile("ld.acquire.gpu.u32 %0, [%1];" : "=r"(v) : "l"(ctr) : "memory");
    while (v < target) {
        __nanosleep(32);
        asm volatile("ld.acquire.gpu.u32 %0, [%1];" : "=r"(v) : "l"(ctr) : "memory");
    }
}

__device__ __forceinline__ void gemm_tile(const char* smem, int aoff_hi, int aoff_lo,
                                          int woff_hi, int woff_lo,
                                          int m_base, int n_base, int grp, int tg,
                                          float acc[4][4]) {
    const char* arow = smem + (m_base + grp) * STRB + tg * 4;
    #pragma unroll
    for (int ks = 0; ks < 8; ks++) {
        const int kb = ks * 32;
        uint32_t a_hi[4], a_lo[4];
        a_hi[0] = *(const uint32_t*)(arow + aoff_hi + kb);
        a_hi[1] = *(const uint32_t*)(arow + aoff_hi + 8 * STRB + kb);
        a_hi[2] = *(const uint32_t*)(arow + aoff_hi + kb + 16);
        a_hi[3] = *(const uint32_t*)(arow + aoff_hi + 8 * STRB + kb + 16);
        a_lo[0] = *(const uint32_t*)(arow + aoff_lo + kb);
        a_lo[1] = *(const uint32_t*)(arow + aoff_lo + 8 * STRB + kb);
        a_lo[2] = *(const uint32_t*)(arow + aoff_lo + kb + 16);
        a_lo[3] = *(const uint32_t*)(arow + aoff_lo + 8 * STRB + kb + 16);
        #pragma unroll
        for (int nt = 0; nt < 4; nt++) {
            const char* brow = smem + (n_base + nt * 8 + grp) * STRB + tg * 4 + kb;
            uint32_t b_hi[2], b_lo[2];
            b_hi[0] = *(const uint32_t*)(brow + woff_hi);
            b_hi[1] = *(const uint32_t*)(brow + woff_hi + 16);
            b_lo[0] = *(const uint32_t*)(brow + woff_lo);
            b_lo[1] = *(const uint32_t*)(brow + woff_lo + 16);
            mma_bf16(acc[nt], a_hi, b_hi);
            mma_bf16(acc[nt], a_hi, b_lo);
            mma_bf16(acc[nt], a_lo, b_hi);
        }
    }
}

// stage a 64x128 bf16 hi/lo slice (gmem row stride 512) into SMEM tiles
__device__ __forceinline__ void stage_tile(char* smem, int dst_hi, int dst_lo,
                                           const __nv_bfloat16* sh,
                                           const __nv_bfloat16* sl, int tid) {
    #pragma unroll
    for (int it = 0; it < 4; it++) {
        int idx = tid + it * NTHR;       // 0..1023
        int r   = idx >> 4;              // 0..63
        int c16 = idx & 15;              // 16 units/row = 128 bf16
        uint4 vh = *(const uint4*)(sh + (size_t)r * 512 + c16 * 8);
        uint4 vl = *(const uint4*)(sl + (size_t)r * 512 + c16 * 8);
        int o = r * STRB + c16 * 16;
        *(uint4*)(smem + dst_hi + o) = vh;
        *(uint4*)(smem + dst_lo + o) = vl;
    }
}

extern "C" __global__ void __launch_bounds__(NTHR, 1)
lstm_local_kernel(const float* __restrict__ x,
                  const float* __restrict__ hidden0,
                  const float* __restrict__ cell0,
                  const float* __restrict__ W,
                  const float* __restrict__ bias,
                  float* __restrict__ out)
{
    extern __shared__ char smem[];
    float* sbias = (float*)(smem + SM_BIAS);

    const int tid = threadIdx.x;
    const int bid = blockIdx.x;
    const int cg  = bid >> 2;
    const int kg  = bid & 3;
    const int wid = tid >> 5;
    const int lid = tid & 31;
    const int grp = lid >> 2;
    const int tg  = lid & 3;
    const int m_base = (wid >> 1) * 16;
    const int n_base = (wid & 1) * 32;

    // elementwise ownership: CTA (cg,kg) owns h-cols cg*16 + kg*4 + [0,4)
    const int eb  = tid >> 2;
    const int ejj = tid & 3;
    const int ej  = cg * 16 + kg * 4 + ejj;

    // n' -> actual gate column: col(n') = (n'>>4)*512 + cg*16 + (n'&15)
    // ---- init: W_x / W_h slices -> SMEM hi/lo [n'][k] ----
    {
        for (int idx = tid; idx < KSL * 64; idx += NTHR) {
            int n = idx & 63;
            int k = idx >> 6;
            int col = (n >> 4) * 512 + cg * 16 + (n & 15);
            int o = n * STRB + k * 2;
            float w0 = W[(size_t)(kg * KSL + k) * G4 + col];
            __nv_bfloat16 h0 = __float2bfloat16_rn(w0);
            *(__nv_bfloat16*)(smem + SM_WX_HI + o) = h0;
            *(__nv_bfloat16*)(smem + SM_WX_LO + o) = __float2bfloat16_rn(w0 - __bfloat162float(h0));
            float w1 = W[(size_t)(512 + kg * KSL + k) * G4 + col];
            __nv_bfloat16 h1 = __float2bfloat16_rn(w1);
            *(__nv_bfloat16*)(smem + SM_WH_HI + o) = h1;
            *(__nv_bfloat16*)(smem + SM_WH_LO + o) = __float2bfloat16_rn(w1 - __bfloat162float(h1));
        }
    }
    if (tid < 16) {
        int gate = tid >> 2;
        int jj   = tid & 3;
        sbias[tid] = bias[gate * H_SZ + cg * 16 + kg * 4 + jj];
    }
    // ---- pre-split x -> bf16 hi/lo (grid-strided) ----
    {
        const float4* x4 = (const float4*)x;
        const int n4 = T_STEPS * B_SZ * I_SZ / 4;
        for (int i = bid * NTHR + tid; i < n4; i += NCTA * NTHR) {
            float4 v = x4[i];
            __nv_bfloat16 h0 = __float2bfloat16_rn(v.x);
            __nv_bfloat16 h1 = __float2bfloat16_rn(v.y);
            __nv_bfloat16 h2 = __float2bfloat16_rn(v.z);
            __nv_bfloat16 h3 = __float2bfloat16_rn(v.w);
            __nv_bfloat162* dh = (__nv_bfloat162*)(g_x_hi + 4 * (size_t)i);
            dh[0] = __nv_bfloat162(h0, h1);
            dh[1] = __nv_bfloat162(h2, h3);
            __nv_bfloat162* dl = (__nv_bfloat162*)(g_x_lo + 4 * (size_t)i);
            dl[0] = __nv_bfloat162(__float2bfloat16_rn(v.x - __bfloat162float(h0)),
                                   __float2bfloat16_rn(v.y - __bfloat162float(h1)));
            dl[1] = __nv_bfloat162(__float2bfloat16_rn(v.z - __bfloat162float(h2)),
                                   __float2bfloat16_rn(v.w - __bfloat162float(h3)));
        }
    }
    // ---- state init: h0 -> parity 1 buffers ----
    float c_state = cell0[eb * H_SZ + ej];
    {
        float hv = hidden0[eb * H_SZ + ej];
        __nv_bfloat16 hh = __float2bfloat16_rn(hv);
        g_h_hi[1][eb * H_SZ + ej] = hh;
        g_h_lo[1][eb * H_SZ + ej] = __float2bfloat16_rn(hv - __bfloat162float(hh));
    }
    float h_last = 0.0f;

    // ---- init grid barrier (once): presplit + h0 visible ----
    __syncthreads();
    if (tid == 0) {
        signal(&g_init);
        wait_ge(&g_init, NCTA);
    }
    __syncthreads();

    // ---- prologue: xpart(0) into slot 0 ----
    {
        size_t off = (size_t)kg * KSL;
        stage_tile(smem, SM_AX_HI, SM_AX_LO, g_x_hi + off, g_x_lo + off, tid);
        __syncthreads();
        float acc[4][4];
        #pragma unroll
        for (int i = 0; i < 4; i++) { acc[i][0]=0.f; acc[i][1]=0.f; acc[i][2]=0.f; acc[i][3]=0.f; }
        gemm_tile(smem, SM_AX_HI, SM_AX_LO, SM_WX_HI, SM_WX_LO, m_base, n_base, grp, tg, acc);
        float* xp = g_xp[0][kg];
        #pragma unroll
        for (int nt = 0; nt < 4; nt++) {
            int col = cg * 64 + n_base + nt * 8 + tg * 2;
            int b0  = m_base + grp;
            xp[col * B_SZ + b0]           = acc[nt][0];
            xp[(col + 1) * B_SZ + b0]     = acc[nt][1];
            xp[col * B_SZ + b0 + 8]       = acc[nt][2];
            xp[(col + 1) * B_SZ + b0 + 8] = acc[nt][3];
        }
    }
    __syncthreads();

    // ---- time loop ----
    for (int t = 0; t < T_STEPS; t++) {
        const int par = t & 1;

        // 1) x-block: xpart(t+1) into slot (t+1)%3
        if (t + 1 < T_STEPS) {
            size_t off = (size_t)(t + 1) * B_SZ * I_SZ + kg * KSL;
            stage_tile(smem, SM_AX_HI, SM_AX_LO, g_x_hi + off, g_x_lo + off, tid);
            __syncthreads();
            float acc[4][4];
            #pragma unroll
            for (int i = 0; i < 4; i++) { acc[i][0]=0.f; acc[i][1]=0.f; acc[i][2]=0.f; acc[i][3]=0.f; }
            gemm_tile(smem, SM_AX_HI, SM_AX_LO, SM_WX_HI, SM_WX_LO, m_base, n_base, grp, tg, acc);
            float* xp = g_xp[(t + 1) % 3][kg];
            #pragma unroll
            for (int nt = 0; nt < 4; nt++) {
                int col = cg * 64 + n_base + nt * 8 + tg * 2;
                int b0  = m_base + grp;
                xp[col * B_SZ + b0]           = acc[nt][0];
                xp[(col + 1) * B_SZ + b0]     = acc[nt][1];
                xp[col * B_SZ + b0 + 8]       = acc[nt][2];
                xp[(col + 1) * B_SZ + b0 + 8] = acc[nt][3];
            }
            __syncthreads();
        }

        // 2) localized elem-wait: h(t-1) producers = cgs [kg*8, kg*8+8)
        if (t > 0 && tid < 8) {
            wait_ge(&g_elem[(kg * 8 + tid) * CPAD], 4u * (unsigned)t);
        }
        __syncthreads();

        // 3) h-block: stage h(t-1) (parity par^1), GEMM, hpart -> g_hp[par][kg]
        {
            const __nv_bfloat16* sh = g_h_hi[par ^ 1] + kg * KSL;
            const __nv_bfloat16* sl = g_h_lo[par ^ 1] + kg * KSL;
            stage_tile(smem, SM_AH_HI, SM_AH_LO, sh, sl, tid);
            __syncthreads();
            float acc[4][4];
            #pragma unroll
            for (int i = 0; i < 4; i++) { acc[i][0]=0.f; acc[i][1]=0.f; acc[i][2]=0.f; acc[i][3]=0.f; }
            gemm_tile(smem, SM_AH_HI, SM_AH_LO, SM_WH_HI, SM_WH_LO, m_base, n_base, grp, tg, acc);
            float* hp = g_hp[par][kg];
            #pragma unroll
            for (int nt = 0; nt < 4; nt++) {
                int col = cg * 64 + n_base + nt * 8 + tg * 2;
                int b0  = m_base + grp;
                hp[col * B_SZ + b0]           = acc[nt][0];
                hp[(col + 1) * B_SZ + b0]     = acc[nt][1];
                hp[col * B_SZ + b0 + 8]       = acc[nt][2];
                hp[(col + 1) * B_SZ + b0 + 8] = acc[nt][3];
            }
        }
        __syncthreads();
        if (tid == 0) {
            signal(&g_ph[cg * CPAD]);
            wait_ge(&g_ph[cg * CPAD], 4u * (unsigned)(t + 1));
        }
        __syncthreads();

        // 4) elementwise for h-cols cg*16 + kg*4 + [0,4)
        {
            const float* xp0 = g_xp[t % 3][0];
            const float* xp1 = g_xp[t % 3][1];
            const float* xp2 = g_xp[t % 3][2];
            const float* xp3 = g_xp[t % 3][3];
            const float* hp0 = g_hp[par][0];
            const float* hp1 = g_hp[par][1];
            const float* hp2 = g_hp[par][2];
            const float* hp3 = g_hp[par][3];
            float gate[4];
            #pragma unroll
            for (int g = 0; g < 4; g++) {
                int np  = g * 16 + kg * 4 + ejj;           // n' of this gate col
                int idx = (cg * 64 + np) * B_SZ + eb;
                gate[g] = sbias[g * 4 + ejj]
                        + xp0[idx] + xp1[idx] + xp2[idx] + xp3[idx]
                        + hp0[idx] + hp1[idx] + hp2[idx] + hp3[idx];
            }
            float f  = sigmoidf_fast(gate[0]);
            float ii = sigmoidf_fast(gate[1]);
            float cd = tanhf_fast(gate[2]);
            float o  = sigmoidf_fast(gate[3]);
            c_state = f * c_state + ii * cd;
            float h = o * tanhf_fast(c_state);
            h_last = h;
            __nv_bfloat16 hh = __float2bfloat16_rn(h);
            g_h_hi[par][eb * H_SZ + ej] = hh;
            g_h_lo[par][eb * H_SZ + ej] = __float2bfloat16_rn(h - __bfloat162float(hh));
            out[(size_t)t * (B_SZ * H_SZ) + eb * H_SZ + ej] = h;
        }
        __syncthreads();
        if (tid == 0) signal(&g_elem[cg * CPAD]);
    }

    // final states
    {
        size_t base = (size_t)T_STEPS * B_SZ * H_SZ;
        out[base + eb * H_SZ + ej] = h_last;
        out[base + B_SZ * H_SZ + eb * H_SZ + ej] = c_state;
    }
}

extern "C" void kernel_launch(void* const* d_in, const int* in_sizes, int n_in,
                              void* d_out, int out_size)
{
    (void)in_sizes; (void)n_in; (void)out_size;
    const float* x       = (const float*)d_in[0];
    const float* hidden0 = (const float*)d_in[1];
    const float* cell0   = (const float*)d_in[2];
    const float* W       = (const float*)d_in[3];
    const float* bias    = (const float*)d_in[4];
    float* out = (float*)d_out;

    void* a0 = nullptr; void* a1 = nullptr; void* a2 = nullptr;
    cudaGetSymbolAddress(&a0, g_ph);
    cudaGetSymbolAddress(&a1, g_elem);
    cudaGetSymbolAddress(&a2, g_init);
    cudaMemsetAsync(a0, 0, sizeof(unsigned) * 32 * CPAD);
    cudaMemsetAsync(a1, 0, sizeof(unsigned) * 32 * CPAD);
    cudaMemsetAsync(a2, 0, sizeof(unsigned));

    cudaFuncSetAttribute(lstm_local_kernel,
                         cudaFuncAttributeMaxDynamicSharedMemorySize, SM_TOTAL);

    lstm_local_kernel<<<NCTA, NTHR, SM_TOTAL>>>(x, hidden0, cell0, W, bias, out);
}

// round 14
// speedup vs baseline: 1.0880x; 1.0296x over previous
#include <cuda_runtime.h>
#include <cuda_bf16.h>
#include <math.h>
#include <stdint.h>

// LSTM T=512, B=64, I=H=512 on GB300 (sm_103a via compute_103, HMMA path).
// R14 = R13 (best passing, 3403us) + ONE change: all GEMM fragment loads go
// through ldmatrix (A: m8n8.x4 hi/lo, B: m8n8.x2 per n8-tile hi/lo), replacing
// 24 scalar LDS.32 + address IMADs per warp-kstep with 10 ldmatrix ops.
// Lane->address maps derived to reproduce the exact manual fragment layout;
// bank-conflict-free at STRB=272 (row offsets r*68 words == r*4 mod 32).

#define T_STEPS 512
#define B_SZ    64
#define H_SZ    512
#define I_SZ    512
#define G4      2048
#define NCTA    128
#define NTHR    256
#define KSL     128

#define STRB    272
#define TILEB   (64 * STRB)
#define SM_BIAS 0
#define SM_AX_HI 64
#define SM_AX_LO (SM_AX_HI + TILEB)
#define SM_AH_HI (SM_AX_LO + TILEB)
#define SM_AH_LO (SM_AH_HI + TILEB)
#define SM_WX_HI (SM_AH_LO + TILEB)
#define SM_WX_LO (SM_WX_HI + TILEB)
#define SM_WH_HI (SM_WX_LO + TILEB)
#define SM_WH_LO (SM_WH_HI + TILEB)
#define SM_TOTAL (SM_WH_LO + TILEB)   // 139328

#define CPAD 32

__device__ __align__(16) __nv_bfloat16 g_x_hi[T_STEPS * B_SZ * I_SZ];
__device__ __align__(16) __nv_bfloat16 g_x_lo[T_STEPS * B_SZ * I_SZ];
__device__ __align__(16) __nv_bfloat16 g_h_hi[2][B_SZ * H_SZ];
__device__ __align__(16) __nv_bfloat16 g_h_lo[2][B_SZ * H_SZ];
__device__ float g_xp[3][4][G4 * B_SZ];
__device__ float g_hp[2][4][G4 * B_SZ];
__device__ unsigned g_init;
__device__ unsigned g_ph[32 * CPAD];
__device__ unsigned g_elem[32 * CPAD];

__device__ __forceinline__ float sigmoidf_fast(float x) {
    return 1.0f / (1.0f + __expf(-x));
}
__device__ __forceinline__ float tanhf_fast(float x) {
    return 2.0f / (1.0f + __expf(-2.0f * x)) - 1.0f;
}
__device__ __forceinline__ void mma_bf16(float* d, const uint32_t* a, const uint32_t* b) {
    asm volatile(
        "mma.sync.aligned.m16n8k16.row.col.f32.bf16.bf16.f32 "
        "{%0,%1,%2,%3}, {%4,%5,%6,%7}, {%8,%9}, {%0,%1,%2,%3};"
        : "+f"(d[0]), "+f"(d[1]), "+f"(d[2]), "+f"(d[3])
        : "r"(a[0]), "r"(a[1]), "r"(a[2]), "r"(a[3]), "r"(b[0]), "r"(b[1]));
}
__device__ __forceinline__ void ldmatrix_x4(uint32_t r[4], uint32_t addr) {
    asm volatile("ldmatrix.sync.aligned.m8n8.x4.shared.b16 {%0,%1,%2,%3}, [%4];"
                 : "=r"(r[0]), "=r"(r[1]), "=r"(r[2]), "=r"(r[3]) : "r"(addr));
}
__device__ __forceinline__ void ldmatrix_x2(uint32_t r[2], uint32_t addr) {
    asm volatile("ldmatrix.sync.aligned.m8n8.x2.shared.b16 {%0,%1}, [%2];"
                 : "=r"(r[0]), "=r"(r[1]) : "r"(addr));
}
__device__ __forceinline__ uint32_t smem_u32(const void* p) {
    uint32_t a;
    asm("{ .reg .u64 t; cvta.to.shared.u64 t, %1; cvt.u32.u64 %0, t; }" : "=r"(a) : "l"(p));
    return a;
}
__device__ __forceinline__ void signal(unsigned* ctr) {
    asm volatile("red.release.gpu.add.u32 [%0], 1;" :: "l"(ctr) : "memory");
}
__device__ __forceinline__ void wait_ge(unsigned* ctr, unsigned target) {
    unsigned v;
    asm volatile("ld.acquire.gpu.u32 %0, [%1];" : "=r"(v) : "l"(ctr) : "memory");
    while (v < target) {
        __nanosleep(32);
        asm volatile("ld.acquire.gpu.u32 %0, [%1];" : "=r"(v) : "l"(ctr) : "memory");
    }
}

// 64x64x128 3-pass bf16-split GEMM; fragments via ldmatrix.
// a_lane = sbase + (m_base + (lid&15))*STRB + (lid>>4)*16
// b_lane = sbase + (n_base + (lid&7))*STRB + ((lid>>3)&1)*16
__device__ __forceinline__ void gemm_tile(uint32_t a_lane, uint32_t b_lane,
                                          int aoff_hi, int aoff_lo,
                                          int woff_hi, int woff_lo,
                                          float acc[4][4]) {
    #pragma unroll
    for (int ks = 0; ks < 8; ks++) {
        const int kb = ks * 32;
        uint32_t a_hi[4], a_lo[4];
        ldmatrix_x4(a_hi, a_lane + aoff_hi + kb);
        ldmatrix_x4(a_lo, a_lane + aoff_lo + kb);
        #pragma unroll
        for (int nt = 0; nt < 4; nt++) {
            uint32_t b_hi[2], b_lo[2];
            ldmatrix_x2(b_hi, b_lane + nt * (8 * STRB) + woff_hi + kb);
            ldmatrix_x2(b_lo, b_lane + nt * (8 * STRB) + woff_lo + kb);
            mma_bf16(acc[nt], a_hi, b_hi);
            mma_bf16(acc[nt], a_hi, b_lo);
            mma_bf16(acc[nt], a_lo, b_hi);
        }
    }
}

// stage a 64x128 bf16 hi/lo slice (gmem row stride 512) into SMEM tiles
__device__ __forceinline__ void stage_tile(char* smem, int dst_hi, int dst_lo,
                                           const __nv_bfloat16* sh,
                                           const __nv_bfloat16* sl, int tid) {
    #pragma unroll
    for (int it = 0; it < 4; it++) {
        int idx = tid + it * NTHR;       // 0..1023
        int r   = idx >> 4;
        int c16 = idx & 15;
        uint4 vh = *(const uint4*)(sh + (size_t)r * 512 + c16 * 8);
        uint4 vl = *(const uint4*)(sl + (size_t)r * 512 + c16 * 8);
        int o = r * STRB + c16 * 16;
        *(uint4*)(smem + dst_hi + o) = vh;
        *(uint4*)(smem + dst_lo + o) = vl;
    }
}

extern "C" __global__ void __launch_bounds__(NTHR, 1)
lstm_ldsm_kernel(const float* __restrict__ x,
                 const float* __restrict__ hidden0,
                 const float* __restrict__ cell0,
                 const float* __restrict__ W,
                 const float* __restrict__ bias,
                 float* __restrict__ out)
{
    extern __shared__ char smem[];
    float* sbias = (float*)(smem + SM_BIAS);
    const uint32_t sbase = smem_u32(smem);

    const int tid = threadIdx.x;
    const int bid = blockIdx.x;
    const int cg  = bid >> 2;
    const int kg  = bid & 3;
    const int wid = tid >> 5;
    const int lid = tid & 31;
    const int m_base = (wid >> 1) * 16;
    const int n_base = (wid & 1) * 32;
    const int grp = lid >> 2;
    const int tg  = lid & 3;

    // ldmatrix lane base addresses
    const uint32_t a_lane = sbase + (uint32_t)(m_base + (lid & 15)) * STRB + (uint32_t)(lid >> 4) * 16;
    const uint32_t b_lane = sbase + (uint32_t)(n_base + (lid & 7)) * STRB + (uint32_t)((lid >> 3) & 1) * 16;

    // elementwise ownership: CTA (cg,kg) owns h-cols cg*16 + kg*4 + [0,4)
    const int eb  = tid >> 2;
    const int ejj = tid & 3;
    const int ej  = cg * 16 + kg * 4 + ejj;

    // ---- init: W_x / W_h slices -> SMEM hi/lo [n'][k] ----
    {
        for (int idx = tid; idx < KSL * 64; idx += NTHR) {
            int n = idx & 63;
            int k = idx >> 6;
            int col = (n >> 4) * 512 + cg * 16 + (n & 15);
            int o = n * STRB + k * 2;
            float w0 = W[(size_t)(kg * KSL + k) * G4 + col];
            __nv_bfloat16 h0 = __float2bfloat16_rn(w0);
            *(__nv_bfloat16*)(smem + SM_WX_HI + o) = h0;
            *(__nv_bfloat16*)(smem + SM_WX_LO + o) = __float2bfloat16_rn(w0 - __bfloat162float(h0));
            float w1 = W[(size_t)(512 + kg * KSL + k) * G4 + col];
            __nv_bfloat16 h1 = __float2bfloat16_rn(w1);
            *(__nv_bfloat16*)(smem + SM_WH_HI + o) = h1;
            *(__nv_bfloat16*)(smem + SM_WH_LO + o) = __float2bfloat16_rn(w1 - __bfloat162float(h1));
        }
    }
    if (tid < 16) {
        int gate = tid >> 2;
        int jj   = tid & 3;
        sbias[tid] = bias[gate * H_SZ + cg * 16 + kg * 4 + jj];
    }
    // ---- pre-split x -> bf16 hi/lo (grid-strided) ----
    {
        const float4* x4 = (const float4*)x;
        const int n4 = T_STEPS * B_SZ * I_SZ / 4;
        for (int i = bid * NTHR + tid; i < n4; i += NCTA * NTHR) {
            float4 v = x4[i];
            __nv_bfloat16 h0 = __float2bfloat16_rn(v.x);
            __nv_bfloat16 h1 = __float2bfloat16_rn(v.y);
            __nv_bfloat16 h2 = __float2bfloat16_rn(v.z);
            __nv_bfloat16 h3 = __float2bfloat16_rn(v.w);
            __nv_bfloat162* dh = (__nv_bfloat162*)(g_x_hi + 4 * (size_t)i);
            dh[0] = __nv_bfloat162(h0, h1);
            dh[1] = __nv_bfloat162(h2, h3);
            __nv_bfloat162* dl = (__nv_bfloat162*)(g_x_lo + 4 * (size_t)i);
            dl[0] = __nv_bfloat162(__float2bfloat16_rn(v.x - __bfloat162float(h0)),
                                   __float2bfloat16_rn(v.y - __bfloat162float(h1)));
            dl[1] = __nv_bfloat162(__float2bfloat16_rn(v.z - __bfloat162float(h2)),
                                   __float2bfloat16_rn(v.w - __bfloat162float(h3)));
        }
    }
    // ---- state init: h0 -> parity 1 buffers ----
    float c_state = cell0[eb * H_SZ + ej];
    {
        float hv = hidden0[eb * H_SZ + ej];
        __nv_bfloat16 hh = __float2bfloat16_rn(hv);
        g_h_hi[1][eb * H_SZ + ej] = hh;
        g_h_lo[1][eb * H_SZ + ej] = __float2bfloat16_rn(hv - __bfloat162float(hh));
    }
    float h_last = 0.0f;

    // ---- init grid barrier ----
    __syncthreads();
    if (tid == 0) {
        signal(&g_init);
        wait_ge(&g_init, NCTA);
    }
    __syncthreads();

    // ---- prologue: xpart(0) into slot 0 ----
    {
        size_t off = (size_t)kg * KSL;
        stage_tile(smem, SM_AX_HI, SM_AX_LO, g_x_hi + off, g_x_lo + off, tid);
        __syncthreads();
        float acc[4][4];
        #pragma unroll
        for (int i = 0; i < 4; i++) { acc[i][0]=0.f; acc[i][1]=0.f; acc[i][2]=0.f; acc[i][3]=0.f; }
        gemm_tile(a_lane, b_lane, SM_AX_HI, SM_AX_LO, SM_WX_HI, SM_WX_LO, acc);
        float* xp = g_xp[0][kg];
        #pragma unroll
        for (int nt = 0; nt < 4; nt++) {
            int col = cg * 64 + n_base + nt * 8 + tg * 2;
            int b0  = m_base + grp;
            xp[col * B_SZ + b0]           = acc[nt][0];
            xp[(col + 1) * B_SZ + b0]     = acc[nt][1];
            xp[col * B_SZ + b0 + 8]       = acc[nt][2];
            xp[(col + 1) * B_SZ + b0 + 8] = acc[nt][3];
        }
    }
    __syncthreads();

    // ---- time loop ----
    for (int t = 0; t < T_STEPS; t++) {
        const int par = t & 1;

        // 1) x-block: xpart(t+1) into slot (t+1)%3
        if (t + 1 < T_STEPS) {
            size_t off = (size_t)(t + 1) * B_SZ * I_SZ + kg * KSL;
            stage_tile(smem, SM_AX_HI, SM_AX_LO, g_x_hi + off, g_x_lo + off, tid);
            __syncthreads();
            float acc[4][4];
            #pragma unroll
            for (int i = 0; i < 4; i++) { acc[i][0]=0.f; acc[i][1]=0.f; acc[i][2]=0.f; acc[i][3]=0.f; }
            gemm_tile(a_lane, b_lane, SM_AX_HI, SM_AX_LO, SM_WX_HI, SM_WX_LO, acc);
            float* xp = g_xp[(t + 1) % 3][kg];
            #pragma unroll
            for (int nt = 0; nt < 4; nt++) {
                int col = cg * 64 + n_base + nt * 8 + tg * 2;
                int b0  = m_base + grp;
                xp[col * B_SZ + b0]           = acc[nt][0];
                xp[(col + 1) * B_SZ + b0]     = acc[nt][1];
                xp[col * B_SZ + b0 + 8]       = acc[nt][2];
                xp[(col + 1) * B_SZ + b0 + 8] = acc[nt][3];
            }
            __syncthreads();
        }

        // 2) localized elem-wait: h(t-1) producers = cgs [kg*8, kg*8+8)
        if (t > 0 && tid < 8) {
            wait_ge(&g_elem[(kg * 8 + tid) * CPAD], 4u * (unsigned)t);
        }
        __syncthreads();

        // 3) h-block
        {
            const __nv_bfloat16* sh = g_h_hi[par ^ 1] + kg * KSL;
            const __nv_bfloat16* sl = g_h_lo[par ^ 1] + kg * KSL;
            stage_tile(smem, SM_AH_HI, SM_AH_LO, sh, sl, tid);
            __syncthreads();
            float acc[4][4];
            #pragma unroll
            for (int i = 0; i < 4; i++) { acc[i][0]=0.f; acc[i][1]=0.f; acc[i][2]=0.f; acc[i][3]=0.f; }
            gemm_tile(a_lane, b_lane, SM_AH_HI, SM_AH_LO, SM_WH_HI, SM_WH_LO, acc);
            float* hp = g_hp[par][kg];
            #pragma unroll
            for (int nt = 0; nt < 4; nt++) {
                int col = cg * 64 + n_base + nt * 8 + tg * 2;
                int b0  = m_base + grp;
                hp[col * B_SZ + b0]           = acc[nt][0];
                hp[(col + 1) * B_SZ + b0]     = acc[nt][1];
                hp[col * B_SZ + b0 + 8]       = acc[nt][2];
                hp[(col + 1) * B_SZ + b0 + 8] = acc[nt][3];
            }
        }
        __syncthreads();
        if (tid == 0) {
            signal(&g_ph[cg * CPAD]);
            wait_ge(&g_ph[cg * CPAD], 4u * (unsigned)(t + 1));
        }
        __syncthreads();

        // 4) elementwise for h-cols cg*16 + kg*4 + [0,4)
        {
            const float* xp0 = g_xp[t % 3][0];
            const float* xp1 = g_xp[t % 3][1];
            const float* xp2 = g_xp[t % 3][2];
            const float* xp3 = g_xp[t % 3][3];
            const float* hp0 = g_hp[par][0];
            const float* hp1 = g_hp[par][1];
            const float* hp2 = g_hp[par][2];
            const float* hp3 = g_hp[par][3];
            float gate[4];
            #pragma unroll
            for (int g = 0; g < 4; g++) {
                int np  = g * 16 + kg * 4 + ejj;
                int idx = (cg * 64 + np) * B_SZ + eb;
                gate[g] = sbias[g * 4 + ejj]
                        + xp0[idx] + xp1[idx] + xp2[idx] + xp3[idx]
                        + hp0[idx] + hp1[idx] + hp2[idx] + hp3[idx];
            }
            float f  = sigmoidf_fast(gate[0]);
            float ii = sigmoidf_fast(gate[1]);
            float cd = tanhf_fast(gate[2]);
            float o  = sigmoidf_fast(gate[3]);
            c_state = f * c_state + ii * cd;
            float h = o * tanhf_fast(c_state);
            h_last = h;
            __nv_bfloat16 hh = __float2bfloat16_rn(h);
            g_h_hi[par][eb * H_SZ + ej] = hh;
            g_h_lo[par][eb * H_SZ + ej] = __float2bfloat16_rn(h - __bfloat162float(hh));
            out[(size_t)t * (B_SZ * H_SZ) + eb * H_SZ + ej] = h;
        }
        __syncthreads();
        if (tid == 0) signal(&g_elem[cg * CPAD]);
    }

    // final states
    {
        size_t base = (size_t)T_STEPS * B_SZ * H_SZ;
        out[base + eb * H_SZ + ej] = h_last;
        out[base + B_SZ * H_SZ + eb * H_SZ + ej] = c_state;
    }
}

extern "C" void kernel_launch(void* const* d_in, const int* in_sizes, int n_in,
                              void* d_out, int out_size)
{
    (void)in_sizes; (void)n_in; (void)out_size;
    const float* x       = (const float*)d_in[0];
    const float* hidden0 = (const float*)d_in[1];
    const float* cell0   = (const float*)d_in[2];
    const float* W       = (const float*)d_in[3];
    const float* bias    = (const float*)d_in[4];
    float* out = (float*)d_out;

    void* a0 = nullptr; void* a1 = nullptr; void* a2 = nullptr;
    cudaGetSymbolAddress(&a0, g_ph);
    cudaGetSymbolAddress(&a1, g_elem);
    cudaGetSymbolAddress(&a2, g_init);
    cudaMemsetAsync(a0, 0, sizeof(unsigned) * 32 * CPAD);
    cudaMemsetAsync(a1, 0, sizeof(unsigned) * 32 * CPAD);
    cudaMemsetAsync(a2, 0, sizeof(unsigned));

    cudaFuncSetAttribute(lstm_ldsm_kernel,
                         cudaFuncAttributeMaxDynamicSharedMemorySize, SM_TOTAL);

    lstm_ldsm_kernel<<<NCTA, NTHR, SM_TOTAL>>>(x, hidden0, cell0, W, bias, out);
}

// round 15
// speedup vs baseline: 1.1957x; 1.0990x over previous
#include <cuda_runtime.h>
#include <cuda_bf16.h>
#include <math.h>
#include <stdint.h>

// LSTM T=512, B=64, I=H=512 on GB300 (sm_103a via compute_103, HMMA path).
// R15 = R14 (best, 3305us) + ONE structural change: the x-partial never leaves
// registers. x-GEMM for step t+1 runs at the END of iteration t into xacc[4][4];
// iteration t+1's h-GEMM initializes its accumulators from xacc, so hp is the
// COMBINED (x+h) partial. g_xp global arrays, their stores, and half the
// elementwise gather are deleted. Everything else identical to R14.

#define T_STEPS 512
#define B_SZ    64
#define H_SZ    512
#define I_SZ    512
#define G4      2048
#define NCTA    128
#define NTHR    256
#define KSL     128

#define STRB    272
#define TILEB   (64 * STRB)
#define SM_BIAS 0
#define SM_AX_HI 64
#define SM_AX_LO (SM_AX_HI + TILEB)
#define SM_AH_HI (SM_AX_LO + TILEB)
#define SM_AH_LO (SM_AH_HI + TILEB)
#define SM_WX_HI (SM_AH_LO + TILEB)
#define SM_WX_LO (SM_WX_HI + TILEB)
#define SM_WH_HI (SM_WX_LO + TILEB)
#define SM_WH_LO (SM_WH_HI + TILEB)
#define SM_TOTAL (SM_WH_LO + TILEB)   // 139328

#define CPAD 32

__device__ __align__(16) __nv_bfloat16 g_x_hi[T_STEPS * B_SZ * I_SZ];
__device__ __align__(16) __nv_bfloat16 g_x_lo[T_STEPS * B_SZ * I_SZ];
__device__ __align__(16) __nv_bfloat16 g_h_hi[2][B_SZ * H_SZ];
__device__ __align__(16) __nv_bfloat16 g_h_lo[2][B_SZ * H_SZ];
__device__ float g_hp[2][4][G4 * B_SZ];     // combined x+h partials [parity][kg]
__device__ unsigned g_init;
__device__ unsigned g_ph[32 * CPAD];
__device__ unsigned g_elem[32 * CPAD];

__device__ __forceinline__ float sigmoidf_fast(float x) {
    return 1.0f / (1.0f + __expf(-x));
}
__device__ __forceinline__ float tanhf_fast(float x) {
    return 2.0f / (1.0f + __expf(-2.0f * x)) - 1.0f;
}
__device__ __forceinline__ void mma_bf16(float* d, const uint32_t* a, const uint32_t* b) {
    asm volatile(
        "mma.sync.aligned.m16n8k16.row.col.f32.bf16.bf16.f32 "
        "{%0,%1,%2,%3}, {%4,%5,%6,%7}, {%8,%9}, {%0,%1,%2,%3};"
        : "+f"(d[0]), "+f"(d[1]), "+f"(d[2]), "+f"(d[3])
        : "r"(a[0]), "r"(a[1]), "r"(a[2]), "r"(a[3]), "r"(b[0]), "r"(b[1]));
}
__device__ __forceinline__ void ldmatrix_x4(uint32_t r[4], uint32_t addr) {
    asm volatile("ldmatrix.sync.aligned.m8n8.x4.shared.b16 {%0,%1,%2,%3}, [%4];"
                 : "=r"(r[0]), "=r"(r[1]), "=r"(r[2]), "=r"(r[3]) : "r"(addr));
}
__device__ __forceinline__ void ldmatrix_x2(uint32_t r[2], uint32_t addr) {
    asm volatile("ldmatrix.sync.aligned.m8n8.x2.shared.b16 {%0,%1}, [%2];"
                 : "=r"(r[0]), "=r"(r[1]) : "r"(addr));
}
__device__ __forceinline__ uint32_t smem_u32(const void* p) {
    uint32_t a;
    asm("{ .reg .u64 t; cvta.to.shared.u64 t, %1; cvt.u32.u64 %0, t; }" : "=r"(a) : "l"(p));
    return a;
}
__device__ __forceinline__ void signal(unsigned* ctr) {
    asm volatile("red.release.gpu.add.u32 [%0], 1;" :: "l"(ctr) : "memory");
}
__device__ __forceinline__ void wait_ge(unsigned* ctr, unsigned target) {
    unsigned v;
    asm volatile("ld.acquire.gpu.u32 %0, [%1];" : "=r"(v) : "l"(ctr) : "memory");
    while (v < target) {
        __nanosleep(32);
        asm volatile("ld.acquire.gpu.u32 %0, [%1];" : "=r"(v) : "l"(ctr) : "memory");
    }
}

// 64x64x128 3-pass bf16-split GEMM; fragments via ldmatrix; accumulates into acc.
__device__ __forceinline__ void gemm_tile(uint32_t a_lane, uint32_t b_lane,
                                          int aoff_hi, int aoff_lo,
                                          int woff_hi, int woff_lo,
                                          float acc[4][4]) {
    #pragma unroll
    for (int ks = 0; ks < 8; ks++) {
        const int kb = ks * 32;
        uint32_t a_hi[4], a_lo[4];
        ldmatrix_x4(a_hi, a_lane + aoff_hi + kb);
        ldmatrix_x4(a_lo, a_lane + aoff_lo + kb);
        #pragma unroll
        for (int nt = 0; nt < 4; nt++) {
            uint32_t b_hi[2], b_lo[2];
            ldmatrix_x2(b_hi, b_lane + nt * (8 * STRB) + woff_hi + kb);
            ldmatrix_x2(b_lo, b_lane + nt * (8 * STRB) + woff_lo + kb);
            mma_bf16(acc[nt], a_hi, b_hi);
            mma_bf16(acc[nt], a_hi, b_lo);
            mma_bf16(acc[nt], a_lo, b_hi);
        }
    }
}

__device__ __forceinline__ void stage_tile(char* smem, int dst_hi, int dst_lo,
                                           const __nv_bfloat16* sh,
                                           const __nv_bfloat16* sl, int tid) {
    #pragma unroll
    for (int it = 0; it < 4; it++) {
        int idx = tid + it * NTHR;       // 0..1023
        int r   = idx >> 4;
        int c16 = idx & 15;
        uint4 vh = *(const uint4*)(sh + (size_t)r * 512 + c16 * 8);
        uint4 vl = *(const uint4*)(sl + (size_t)r * 512 + c16 * 8);
        int o = r * STRB + c16 * 16;
        *(uint4*)(smem + dst_hi + o) = vh;
        *(uint4*)(smem + dst_lo + o) = vl;
    }
}

extern "C" __global__ void __launch_bounds__(NTHR, 1)
lstm_fold_kernel(const float* __restrict__ x,
                 const float* __restrict__ hidden0,
                 const float* __restrict__ cell0,
                 const float* __restrict__ W,
                 const float* __restrict__ bias,
                 float* __restrict__ out)
{
    extern __shared__ char smem[];
    float* sbias = (float*)(smem + SM_BIAS);
    const uint32_t sbase = smem_u32(smem);

    const int tid = threadIdx.x;
    const int bid = blockIdx.x;
    const int cg  = bid >> 2;
    const int kg  = bid & 3;
    const int wid = tid >> 5;
    const int lid = tid & 31;
    const int m_base = (wid >> 1) * 16;
    const int n_base = (wid & 1) * 32;
    const int grp = lid >> 2;
    const int tg  = lid & 3;

    const uint32_t a_lane = sbase + (uint32_t)(m_base + (lid & 15)) * STRB + (uint32_t)(lid >> 4) * 16;
    const uint32_t b_lane = sbase + (uint32_t)(n_base + (lid & 7)) * STRB + (uint32_t)((lid >> 3) & 1) * 16;

    // elementwise ownership: CTA (cg,kg) owns h-cols cg*16 + kg*4 + [0,4)
    const int eb  = tid >> 2;
    const int ejj = tid & 3;
    const int ej  = cg * 16 + kg * 4 + ejj;

    // ---- init: W_x / W_h slices -> SMEM hi/lo [n'][k] ----
    {
        for (int idx = tid; idx < KSL * 64; idx += NTHR) {
            int n = idx & 63;
            int k = idx >> 6;
            int col = (n >> 4) * 512 + cg * 16 + (n & 15);
            int o = n * STRB + k * 2;
            float w0 = W[(size_t)(kg * KSL + k) * G4 + col];
            __nv_bfloat16 h0 = __float2bfloat16_rn(w0);
            *(__nv_bfloat16*)(smem + SM_WX_HI + o) = h0;
            *(__nv_bfloat16*)(smem + SM_WX_LO + o) = __float2bfloat16_rn(w0 - __bfloat162float(h0));
            float w1 = W[(size_t)(512 + kg * KSL + k) * G4 + col];
            __nv_bfloat16 h1 = __float2bfloat16_rn(w1);
            *(__nv_bfloat16*)(smem + SM_WH_HI + o) = h1;
            *(__nv_bfloat16*)(smem + SM_WH_LO + o) = __float2bfloat16_rn(w1 - __bfloat162float(h1));
        }
    }
    if (tid < 16) {
        int gate = tid >> 2;
        int jj   = tid & 3;
        sbias[tid] = bias[gate * H_SZ + cg * 16 + kg * 4 + jj];
    }
    // ---- pre-split x -> bf16 hi/lo (grid-strided) ----
    {
        const float4* x4 = (const float4*)x;
        const int n4 = T_STEPS * B_SZ * I_SZ / 4;
        for (int i = bid * NTHR + tid; i < n4; i += NCTA * NTHR) {
            float4 v = x4[i];
            __nv_bfloat16 h0 = __float2bfloat16_rn(v.x);
            __nv_bfloat16 h1 = __float2bfloat16_rn(v.y);
            __nv_bfloat16 h2 = __float2bfloat16_rn(v.z);
            __nv_bfloat16 h3 = __float2bfloat16_rn(v.w);
            __nv_bfloat162* dh = (__nv_bfloat162*)(g_x_hi + 4 * (size_t)i);
            dh[0] = __nv_bfloat162(h0, h1);
            dh[1] = __nv_bfloat162(h2, h3);
            __nv_bfloat162* dl = (__nv_bfloat162*)(g_x_lo + 4 * (size_t)i);
            dl[0] = __nv_bfloat162(__float2bfloat16_rn(v.x - __bfloat162float(h0)),
                                   __float2bfloat16_rn(v.y - __bfloat162float(h1)));
            dl[1] = __nv_bfloat162(__float2bfloat16_rn(v.z - __bfloat162float(h2)),
                                   __float2bfloat16_rn(v.w - __bfloat162float(h3)));
        }
    }
    // ---- state init: h0 -> parity 1 buffers ----
    float c_state = cell0[eb * H_SZ + ej];
    {
        float hv = hidden0[eb * H_SZ + ej];
        __nv_bfloat16 hh = __float2bfloat16_rn(hv);
        g_h_hi[1][eb * H_SZ + ej] = hh;
        g_h_lo[1][eb * H_SZ + ej] = __float2bfloat16_rn(hv - __bfloat162float(hh));
    }
    float h_last = 0.0f;

    // ---- init grid barrier ----
    __syncthreads();
    if (tid == 0) {
        signal(&g_init);
        wait_ge(&g_init, NCTA);
    }
    __syncthreads();

    // ---- prologue: xacc for t=0 (registers only) ----
    float xacc[4][4];
    {
        size_t off = (size_t)kg * KSL;
        stage_tile(smem, SM_AX_HI, SM_AX_LO, g_x_hi + off, g_x_lo + off, tid);
        __syncthreads();
        #pragma unroll
        for (int i = 0; i < 4; i++) { xacc[i][0]=0.f; xacc[i][1]=0.f; xacc[i][2]=0.f; xacc[i][3]=0.f; }
        gemm_tile(a_lane, b_lane, SM_AX_HI, SM_AX_LO, SM_WX_HI, SM_WX_LO, xacc);
    }
    __syncthreads();

    // ---- time loop ----
    for (int t = 0; t < T_STEPS; t++) {
        const int par = t & 1;

        // 1) localized elem-wait: h(t-1) producers = cgs [kg*8, kg*8+8)
        if (t > 0 && tid < 8) {
            wait_ge(&g_elem[(kg * 8 + tid) * CPAD], 4u * (unsigned)t);
        }
        __syncthreads();

        // 2) h-block: acc initialized from xacc (combined x+h partial)
        {
            const __nv_bfloat16* sh = g_h_hi[par ^ 1] + kg * KSL;
            const __nv_bfloat16* sl = g_h_lo[par ^ 1] + kg * KSL;
            stage_tile(smem, SM_AH_HI, SM_AH_LO, sh, sl, tid);
            __syncthreads();
            float acc[4][4];
            #pragma unroll
            for (int i = 0; i < 4; i++) {
                acc[i][0] = xacc[i][0]; acc[i][1] = xacc[i][1];
                acc[i][2] = xacc[i][2]; acc[i][3] = xacc[i][3];
            }
            gemm_tile(a_lane, b_lane, SM_AH_HI, SM_AH_LO, SM_WH_HI, SM_WH_LO, acc);
            float* hp = g_hp[par][kg];
            #pragma unroll
            for (int nt = 0; nt < 4; nt++) {
                int col = cg * 64 + n_base + nt * 8 + tg * 2;
                int b0  = m_base + grp;
                hp[col * B_SZ + b0]           = acc[nt][0];
                hp[(col + 1) * B_SZ + b0]     = acc[nt][1];
                hp[col * B_SZ + b0 + 8]       = acc[nt][2];
                hp[(col + 1) * B_SZ + b0 + 8] = acc[nt][3];
            }
        }
        __syncthreads();
        if (tid == 0) {
            signal(&g_ph[cg * CPAD]);
            wait_ge(&g_ph[cg * CPAD], 4u * (unsigned)(t + 1));
        }
        __syncthreads();

        // 3) elementwise for h-cols cg*16 + kg*4 + [0,4): 4 combined arrays
        {
            const float* hp0 = g_hp[par][0];
            const float* hp1 = g_hp[par][1];
            const float* hp2 = g_hp[par][2];
            const float* hp3 = g_hp[par][3];
            float gate[4];
            #pragma unroll
            for (int g = 0; g < 4; g++) {
                int np  = g * 16 + kg * 4 + ejj;
                int idx = (cg * 64 + np) * B_SZ + eb;
                gate[g] = sbias[g * 4 + ejj]
                        + hp0[idx] + hp1[idx] + hp2[idx] + hp3[idx];
            }
            float f  = sigmoidf_fast(gate[0]);
            float ii = sigmoidf_fast(gate[1]);
            float cd = tanhf_fast(gate[2]);
            float o  = sigmoidf_fast(gate[3]);
            c_state = f * c_state + ii * cd;
            float h = o * tanhf_fast(c_state);
            h_last = h;
            __nv_bfloat16 hh = __float2bfloat16_rn(h);
            g_h_hi[par][eb * H_SZ + ej] = hh;
            g_h_lo[par][eb * H_SZ + ej] = __float2bfloat16_rn(h - __bfloat162float(hh));
            out[(size_t)t * (B_SZ * H_SZ) + eb * H_SZ + ej] = h;
        }
        __syncthreads();
        if (tid == 0) signal(&g_elem[cg * CPAD]);

        // 4) x-block for t+1 (post-elem slack): xacc = x(t+1) @ Wx, registers only
        if (t + 1 < T_STEPS) {
            size_t off = (size_t)(t + 1) * B_SZ * I_SZ + kg * KSL;
            stage_tile(smem, SM_AX_HI, SM_AX_LO, g_x_hi + off, g_x_lo + off, tid);
            __syncthreads();
            #pragma unroll
            for (int i = 0; i < 4; i++) { xacc[i][0]=0.f; xacc[i][1]=0.f; xacc[i][2]=0.f; xacc[i][3]=0.f; }
            gemm_tile(a_lane, b_lane, SM_AX_HI, SM_AX_LO, SM_WX_HI, SM_WX_LO, xacc);
        }
    }

    // final states
    {
        size_t base = (size_t)T_STEPS * B_SZ * H_SZ;
        out[base + eb * H_SZ + ej] = h_last;
        out[base + B_SZ * H_SZ + eb * H_SZ + ej] = c_state;
    }
}

extern "C" void kernel_launch(void* const* d_in, const int* in_sizes, int n_in,
                              void* d_out, int out_size)
{
    (void)in_sizes; (void)n_in; (void)out_size;
    const float* x       = (const float*)d_in[0];
    const float* hidden0 = (const float*)d_in[1];
    const float* cell0   = (const float*)d_in[2];
    const float* W       = (const float*)d_in[3];
    const float* bias    = (const float*)d_in[4];
    float* out = (float*)d_out;

    void* a0 = nullptr; void* a1 = nullptr; void* a2 = nullptr;
    cudaGetSymbolAddress(&a0, g_ph);
    cudaGetSymbolAddress(&a1, g_elem);
    cudaGetSymbolAddress(&a2, g_init);
    cudaMemsetAsync(a0, 0, sizeof(unsigned) * 32 * CPAD);
    cudaMemsetAsync(a1, 0, sizeof(unsigned) * 32 * CPAD);
    cudaMemsetAsync(a2, 0, sizeof(unsigned));

    cudaFuncSetAttribute(lstm_fold_kernel,
                         cudaFuncAttributeMaxDynamicSharedMemorySize, SM_TOTAL);

    lstm_fold_kernel<<<NCTA, NTHR, SM_TOTAL>>>(x, hidden0, cell0, W, bias, out);
}